// round 14
// baseline (speedup 1.0000x reference)
#include <cuda_runtime.h>
#include <cuda_bf16.h>
#include <cstdint>

// Problem constants
#define Bc  4
#define Sc  2048
#define Hc  768
#define NHc 12
#define DHc 64
#define Mc  (Bc * Sc)          // 8192
#define SCALE 0.125f

typedef __nv_bfloat16 bf16;

// =================== helpers ================================================
__device__ __forceinline__ uint32_t smem_u32(const void* p) {
    uint32_t a;
    asm("{ .reg .u64 t; cvta.to.shared.u64 t, %1; cvt.u32.u64 %0, t; }" : "=r"(a) : "l"(p));
    return a;
}
__device__ __forceinline__ void ldm4(uint32_t* r, uint32_t addr) {
    asm volatile("ldmatrix.sync.aligned.m8n8.x4.shared.b16 {%0,%1,%2,%3}, [%4];"
        : "=r"(r[0]), "=r"(r[1]), "=r"(r[2]), "=r"(r[3]) : "r"(addr));
}
__device__ __forceinline__ void ldm4t(uint32_t* r, uint32_t addr) {
    asm volatile("ldmatrix.sync.aligned.m8n8.x4.trans.shared.b16 {%0,%1,%2,%3}, [%4];"
        : "=r"(r[0]), "=r"(r[1]), "=r"(r[2]), "=r"(r[3]) : "r"(addr));
}
__device__ __forceinline__ void mma_bf16(float* d, const uint32_t* a, uint32_t b0, uint32_t b1) {
    asm volatile("mma.sync.aligned.m16n8k16.row.col.f32.bf16.bf16.f32 "
        "{%0,%1,%2,%3}, {%4,%5,%6,%7}, {%8,%9}, {%0,%1,%2,%3};"
        : "+f"(d[0]), "+f"(d[1]), "+f"(d[2]), "+f"(d[3])
        : "r"(a[0]), "r"(a[1]), "r"(a[2]), "r"(a[3]), "r"(b0), "r"(b1));
}
__device__ __forceinline__ uint32_t b2u(__nv_bfloat162 v) {
    uint32_t u; asm("mov.b32 %0, %1;" : "=r"(u) : "r"(*(uint32_t*)&v)); return u;
}
// cp.async (sm_80 baseline -> valid on compute_103)
__device__ __forceinline__ void cp16(uint32_t dst, const void* src) {
    asm volatile("cp.async.cg.shared.global [%0], [%1], 16;" :: "r"(dst), "l"(src));
}
#define CP_COMMIT() asm volatile("cp.async.commit_group;" ::: "memory")
#define CP_WAIT(n)  asm volatile("cp.async.wait_group %0;" :: "n"(n) : "memory")

// =================== scratch (device globals) ================================
__device__ bf16 g_Qhi[(size_t)Bc * NHc * Sc * DHc], g_Qlo[(size_t)Bc * NHc * Sc * DHc];
__device__ bf16 g_Khi[(size_t)Bc * NHc * Sc * DHc], g_Klo[(size_t)Bc * NHc * Sc * DHc];
__device__ bf16 g_Vhi[(size_t)Bc * NHc * Sc * DHc], g_Vlo[(size_t)Bc * NHc * Sc * DHc];
__device__ bf16 g_Ahi[(size_t)Mc * Hc], g_Alo[(size_t)Mc * Hc];          // attn out split
__device__ bf16 g_Xhi[(size_t)Mc * Hc], g_Xlo[(size_t)Mc * Hc];          // x split
__device__ bf16 g_WtHi[(size_t)4 * Hc * Hc], g_WtLo[(size_t)4 * Hc * Hc]; // W^T [z][n][k]

// =================== split kernels ==========================================
__device__ __forceinline__ void split1(float v, bf16& h, bf16& l) {
    h = __float2bfloat16(v);
    l = __float2bfloat16(v - __bfloat162float(h));
}

__global__ __launch_bounds__(256)
void split_x_kernel(const float* __restrict__ X) {
    const int idx = blockIdx.x * 256 + threadIdx.x;
    float4 v = ((const float4*)X)[idx];
    bf16 h0,h1,h2,h3,l0,l1,l2,l3;
    split1(v.x,h0,l0); split1(v.y,h1,l1); split1(v.z,h2,l2); split1(v.w,h3,l3);
    ((__nv_bfloat162*)g_Xhi)[2*idx]   = __halves2bfloat162(h0,h1);
    ((__nv_bfloat162*)g_Xhi)[2*idx+1] = __halves2bfloat162(h2,h3);
    ((__nv_bfloat162*)g_Xlo)[2*idx]   = __halves2bfloat162(l0,l1);
    ((__nv_bfloat162*)g_Xlo)[2*idx+1] = __halves2bfloat162(l2,l3);
}

// transpose + split: Wt[n][k] = W[k][n]
__global__ __launch_bounds__(256)
void split_w_kernel(const float* __restrict__ Wq, const float* __restrict__ Wk,
                    const float* __restrict__ Wv, const float* __restrict__ Wo) {
    __shared__ float t[32][33];
    const int z = blockIdx.z;
    const float* W = (z == 0) ? Wq : (z == 1) ? Wk : (z == 2) ? Wv : Wo;
    bf16* hi = g_WtHi + (size_t)z * Hc * Hc;
    bf16* lo = g_WtLo + (size_t)z * Hc * Hc;
    const int bx = blockIdx.x * 32;     // n block
    const int by = blockIdx.y * 32;     // k block
    const int tx = threadIdx.x & 31, ty = (threadIdx.x >> 5) * 4;
    #pragma unroll
    for (int j = 0; j < 4; j++)
        t[ty + j][tx] = W[(size_t)(by + ty + j) * Hc + bx + tx];
    __syncthreads();
    #pragma unroll
    for (int j = 0; j < 4; j++) {
        float v = t[tx][ty + j];
        bf16 h, l; split1(v, h, l);
        hi[(size_t)(bx + ty + j) * Hc + by + tx] = h;
        lo[(size_t)(bx + ty + j) * Hc + by + tx] = l;
    }
}

// =================== mma.sync bf16 GEMM (split fp32, cp.async pipeline) =====
// MODE 0: fp32 (+bias) row-major.  MODE 1: split bf16 (+bias,*scale) head layout.
// k-chunks of 32 double-buffered via cp.async: chunk c+1 streams in while the
// tensor cores consume chunk c.
#define PADK 40
#define GA_B   ((uint32_t)(128 * PADK * 2))   // 10240B per array
#define GSTG_B (4 * GA_B)                     // Ah,Al,Bh,Bl = 40960B per stage
#define GEMM_SMEM (2 * GSTG_B)                // 81920B

template <int MODE>
__device__ __forceinline__ void mma_gemm_body(
    const bf16* __restrict__ Ahi, const bf16* __restrict__ Alo,
    const bf16* __restrict__ Bhi, const bf16* __restrict__ Blo,
    const float* __restrict__ bias, float scale,
    float* __restrict__ outF, bf16* __restrict__ outHi, bf16* __restrict__ outLo)
{
    extern __shared__ char gsm[];
    const uint32_t sb = smem_u32(gsm);

    const int tid = threadIdx.x, lane = tid & 31, wid = tid >> 5;
    const int warp_m = wid >> 1, warp_n = wid & 1;
    const int m0 = blockIdx.y * 128, n0 = blockIdx.x * 128;

    float d[2][8][4];
    #pragma unroll
    for (int mt = 0; mt < 2; mt++)
        #pragma unroll
        for (int nt = 0; nt < 8; nt++)
            #pragma unroll
            for (int i = 0; i < 4; i++) d[mt][nt][i] = 0.f;

    const int lr = lane & 15, chk = lane >> 4;

    // staging coords: 512 chunks of 16B per array; 2 per thread
    const int r0s = tid >> 1, c0s = tid & 1;                 // chunk 0: rows 0..127, col 0/1
    const int r1s = tid >> 1, c1s = (tid & 1) + 2;           // chunk 1: cols 2/3
    const uint32_t so0 = (uint32_t)(r0s * (PADK * 2) + c0s * 16);
    const uint32_t so1 = (uint32_t)(r1s * (PADK * 2) + c1s * 16);

    auto stage = [&](uint32_t dst, int k0) {
        const size_t gA0 = (size_t)(m0 + r0s) * Hc + k0 + c0s * 8;
        const size_t gA1 = (size_t)(m0 + r1s) * Hc + k0 + c1s * 8;
        const size_t gB0 = (size_t)(n0 + r0s) * Hc + k0 + c0s * 8;
        const size_t gB1 = (size_t)(n0 + r1s) * Hc + k0 + c1s * 8;
        cp16(dst + 0 * GA_B + so0, Ahi + gA0); cp16(dst + 0 * GA_B + so1, Ahi + gA1);
        cp16(dst + 1 * GA_B + so0, Alo + gA0); cp16(dst + 1 * GA_B + so1, Alo + gA1);
        cp16(dst + 2 * GA_B + so0, Bhi + gB0); cp16(dst + 2 * GA_B + so1, Bhi + gB1);
        cp16(dst + 3 * GA_B + so0, Blo + gB0); cp16(dst + 3 * GA_B + so1, Blo + gB1);
    };

    // prologue: stage chunk 0
    stage(sb, 0);
    CP_COMMIT();

    #pragma unroll 1
    for (int c = 0; c < Hc / 32; c++) {
        const uint32_t cur = sb + (uint32_t)(c & 1) * GSTG_B;
        if (c + 1 < Hc / 32) {
            stage(sb + (uint32_t)((c + 1) & 1) * GSTG_B, (c + 1) * 32);
            CP_COMMIT();
            CP_WAIT(1);
        } else {
            CP_WAIT(0);
        }
        __syncthreads();

        #pragma unroll
        for (int s = 0; s < 2; s++) {
            const int kc = s * 16;
            uint32_t ah[2][4], al[2][4];
            #pragma unroll
            for (int mt = 0; mt < 2; mt++) {
                const uint32_t off =
                    (uint32_t)(((warp_m * 32 + mt * 16 + lr) * PADK + kc + chk * 8) * 2);
                ldm4(ah[mt], cur + 0 * GA_B + off);
                ldm4(al[mt], cur + 1 * GA_B + off);
            }
            #pragma unroll
            for (int nt2 = 0; nt2 < 4; nt2++) {
                const uint32_t off =
                    (uint32_t)(((warp_n * 64 + nt2 * 16 + lr) * PADK + kc + chk * 8) * 2);
                uint32_t tb[4];
                ldm4(tb, cur + 2 * GA_B + off);
                #pragma unroll
                for (int mt = 0; mt < 2; mt++) {
                    mma_bf16(d[mt][nt2 * 2],     ah[mt], tb[0], tb[2]);
                    mma_bf16(d[mt][nt2 * 2 + 1], ah[mt], tb[1], tb[3]);
                    mma_bf16(d[mt][nt2 * 2],     al[mt], tb[0], tb[2]);
                    mma_bf16(d[mt][nt2 * 2 + 1], al[mt], tb[1], tb[3]);
                }
                ldm4(tb, cur + 3 * GA_B + off);
                #pragma unroll
                for (int mt = 0; mt < 2; mt++) {
                    mma_bf16(d[mt][nt2 * 2],     ah[mt], tb[0], tb[2]);
                    mma_bf16(d[mt][nt2 * 2 + 1], ah[mt], tb[1], tb[3]);
                }
            }
        }
        __syncthreads();
    }

    const int g = lane >> 2, tg = lane & 3;
    #pragma unroll
    for (int mt = 0; mt < 2; mt++) {
        #pragma unroll
        for (int nt = 0; nt < 8; nt++) {
            const int n  = n0 + warp_n * 64 + nt * 8 + tg * 2;
            const float b0 = bias[n], b1 = bias[n + 1];
            #pragma unroll
            for (int half = 0; half < 2; half++) {
                const int m = m0 + warp_m * 32 + mt * 16 + g + half * 8;
                float v0 = d[mt][nt][half * 2 + 0] + b0;
                float v1 = d[mt][nt][half * 2 + 1] + b1;
                if (MODE == 0) {
                    float2 v; v.x = v0; v.y = v1;
                    *(float2*)(outF + (size_t)m * Hc + n) = v;
                } else {
                    v0 *= scale; v1 *= scale;
                    bf16 h0, l0, h1, l1;
                    split1(v0, h0, l0); split1(v1, h1, l1);
                    const int bb = m >> 11, sI = m & (Sc - 1);
                    const int h = n >> 6, dd = n & 63;
                    const size_t o = (((size_t)(bb * NHc + h)) * Sc + sI) * DHc + dd;
                    *(__nv_bfloat162*)(outHi + o) = __halves2bfloat162(h0, h1);
                    *(__nv_bfloat162*)(outLo + o) = __halves2bfloat162(l0, l1);
                }
            }
        }
    }
}

__global__ __launch_bounds__(256, 2)
void mma_gemm_qkv(const float* __restrict__ bq, const float* __restrict__ bk,
                  const float* __restrict__ bv)
{
    const int z = blockIdx.z;
    const float* bias = (z == 0) ? bq : (z == 1) ? bk : bv;
    bf16* oh = (z == 0) ? g_Qhi : (z == 1) ? g_Khi : g_Vhi;
    bf16* ol = (z == 0) ? g_Qlo : (z == 1) ? g_Klo : g_Vlo;
    const float scale = (z == 0) ? SCALE : 1.0f;
    mma_gemm_body<1>(g_Xhi, g_Xlo,
                     g_WtHi + (size_t)z * Hc * Hc, g_WtLo + (size_t)z * Hc * Hc,
                     bias, scale, nullptr, oh, ol);
}

__global__ __launch_bounds__(256, 2)
void mma_gemm_out(const float* __restrict__ bo, float* __restrict__ out)
{
    mma_gemm_body<0>(g_Ahi, g_Alo,
                     g_WtHi + (size_t)3 * Hc * Hc, g_WtLo + (size_t)3 * Hc * Hc,
                     bo, 1.0f, out, nullptr, nullptr);
}

// =================== flash attention: split-bf16 HMMA (round-11 version) ====
#define KPAD 72                       // bf16 row stride (144B): conflict-free
#define QROW_B (KPAD * 2)             // 144
#define SM_QHI 0
#define SM_QLO 36864                  // 256 rows * 144B
#define SM_KV  73728
#define TILE_B  ((uint32_t)(64 * KPAD * 2))   // 9216B per K/V array
#define BUF_B   (4 * TILE_B)                  // Kh,Kl,Vh,Vl = 36864B
#define ATTN_SMEM (SM_KV + 2 * BUF_B)         // 147456B

__global__ __launch_bounds__(256, 1)
void attn_mma_kernel()
{
    extern __shared__ char smem[];
    const uint32_t sb = smem_u32(smem);

    const int tid = threadIdx.x, lane = tid & 31, wid = tid >> 5;
    const int head = blockIdx.y;
    const int q0   = blockIdx.x * 256;
    const int g = lane >> 2, tg = lane & 3;
    const int lr = lane & 15, chk = lane >> 4;

    const bf16* Qh = g_Qhi + ((size_t)head * Sc + q0) * DHc;
    const bf16* Ql = g_Qlo + ((size_t)head * Sc + q0) * DHc;
    const bf16* Kh = g_Khi + (size_t)head * Sc * DHc;
    const bf16* Kl = g_Klo + (size_t)head * Sc * DHc;
    const bf16* Vh = g_Vhi + (size_t)head * Sc * DHc;
    const bf16* Vl = g_Vlo + (size_t)head * Sc * DHc;

    const int r0s = tid >> 3, c0s = tid & 7;
    const int r1s = (tid + 256) >> 3, c1s = tid & 7;
    const uint32_t so0 = (uint32_t)(r0s * QROW_B + c0s * 16);
    const uint32_t so1 = (uint32_t)(r1s * QROW_B + c1s * 16);

    // prologue: stage Q (256 rows, hi+lo) and K/V tile 0
    {
        #pragma unroll
        for (int p = 0; p < 8; p++) {
            const int idx = p * 256 + tid;
            const int r = idx >> 3, c = idx & 7;
            const uint32_t so = (uint32_t)(r * QROW_B + c * 16);
            const size_t go = (size_t)r * DHc + c * 8;
            cp16(sb + SM_QHI + so, Qh + go);
            cp16(sb + SM_QLO + so, Ql + go);
        }
        const size_t g0 = (size_t)r0s * DHc + c0s * 8;
        const size_t g1 = (size_t)r1s * DHc + c1s * 8;
        const uint32_t b0 = sb + SM_KV;
        cp16(b0 + 0 * TILE_B + so0, Kh + g0); cp16(b0 + 0 * TILE_B + so1, Kh + g1);
        cp16(b0 + 1 * TILE_B + so0, Kl + g0); cp16(b0 + 1 * TILE_B + so1, Kl + g1);
        cp16(b0 + 2 * TILE_B + so0, Vh + g0); cp16(b0 + 2 * TILE_B + so1, Vh + g1);
        cp16(b0 + 3 * TILE_B + so0, Vl + g0); cp16(b0 + 3 * TILE_B + so1, Vl + g1);
        CP_COMMIT();
    }

    float O[2][8][4];
    #pragma unroll
    for (int mt = 0; mt < 2; mt++)
        #pragma unroll
        for (int j = 0; j < 8; j++)
            #pragma unroll
            for (int i = 0; i < 4; i++) O[mt][j][i] = 0.f;
    float lsum[2][2] = {{0.f, 0.f}, {0.f, 0.f}};

    const uint32_t qrow = (uint32_t)((wid * 32 + lr) * QROW_B);

    #pragma unroll 1
    for (int kt = 0; kt < Sc / 64; kt++) {
        const uint32_t cur = sb + SM_KV + (uint32_t)(kt & 1) * BUF_B;

        if (kt + 1 < Sc / 64) {
            const uint32_t nxt = sb + SM_KV + (uint32_t)((kt + 1) & 1) * BUF_B;
            const size_t g0 = (size_t)((kt + 1) * 64 + r0s) * DHc + c0s * 8;
            const size_t g1 = (size_t)((kt + 1) * 64 + r1s) * DHc + c1s * 8;
            cp16(nxt + 0 * TILE_B + so0, Kh + g0); cp16(nxt + 0 * TILE_B + so1, Kh + g1);
            cp16(nxt + 1 * TILE_B + so0, Kl + g0); cp16(nxt + 1 * TILE_B + so1, Kl + g1);
            cp16(nxt + 2 * TILE_B + so0, Vh + g0); cp16(nxt + 2 * TILE_B + so1, Vh + g1);
            cp16(nxt + 3 * TILE_B + so0, Vl + g0); cp16(nxt + 3 * TILE_B + so1, Vl + g1);
            CP_COMMIT();
            CP_WAIT(1);
        } else {
            CP_WAIT(0);
        }
        __syncthreads();

        // scores: S = Q . K^T (Q frags re-read from smem per k-step)
        float S[2][8][4];
        #pragma unroll
        for (int mt = 0; mt < 2; mt++)
            #pragma unroll
            for (int j = 0; j < 8; j++)
                #pragma unroll
                for (int i = 0; i < 4; i++) S[mt][j][i] = 0.f;

        #pragma unroll
        for (int ks = 0; ks < 4; ks++) {
            const uint32_t co = (uint32_t)((ks * 16 + chk * 8) * 2);
            uint32_t qh[2][4], ql[2][4];
            #pragma unroll
            for (int mt = 0; mt < 2; mt++) {
                const uint32_t qoff = qrow + (uint32_t)(mt * 16) * QROW_B + co;
                ldm4(qh[mt], sb + SM_QHI + qoff);
                ldm4(ql[mt], sb + SM_QLO + qoff);
            }
            #pragma unroll
            for (int nb = 0; nb < 4; nb++) {
                const uint32_t ro = (uint32_t)((nb * 16 + lr) * QROW_B);
                uint32_t bh[4], bl[4];
                ldm4(bh, cur + 0 * TILE_B + ro + co);
                ldm4(bl, cur + 1 * TILE_B + ro + co);
                #pragma unroll
                for (int mt = 0; mt < 2; mt++) {
                    mma_bf16(S[mt][nb*2],   qh[mt], bh[0], bh[2]);
                    mma_bf16(S[mt][nb*2+1], qh[mt], bh[1], bh[3]);
                    mma_bf16(S[mt][nb*2],   qh[mt], bl[0], bl[2]);
                    mma_bf16(S[mt][nb*2+1], qh[mt], bl[1], bl[3]);
                    mma_bf16(S[mt][nb*2],   ql[mt], bh[0], bh[2]);
                    mma_bf16(S[mt][nb*2+1], ql[mt], bh[1], bh[3]);
                }
            }
        }

        // fused softmax + PV per 16-key group t
        #pragma unroll
        for (int t = 0; t < 4; t++) {
            uint32_t ah[2][4], al[2][4];
            #pragma unroll
            for (int mt = 0; mt < 2; mt++) {
                #pragma unroll
                for (int jj = 0; jj < 2; jj++) {
                    const int j = 2 * t + jj;
                    const float p0 = __expf(S[mt][j][0]);
                    const float p1 = __expf(S[mt][j][1]);
                    const float p2 = __expf(S[mt][j][2]);
                    const float p3 = __expf(S[mt][j][3]);
                    lsum[mt][0] += p0 + p1;
                    lsum[mt][1] += p2 + p3;
                    float2 f01; f01.x = p0; f01.y = p1;
                    float2 f23; f23.x = p2; f23.y = p3;
                    __nv_bfloat162 h01 = __float22bfloat162_rn(f01);
                    __nv_bfloat162 h23 = __float22bfloat162_rn(f23);
                    float2 r01 = __bfloat1622float2(h01);
                    float2 r23 = __bfloat1622float2(h23);
                    float2 d01; d01.x = p0 - r01.x; d01.y = p1 - r01.y;
                    float2 d23; d23.x = p2 - r23.x; d23.y = p3 - r23.y;
                    ah[mt][jj * 2 + 0] = b2u(h01);
                    ah[mt][jj * 2 + 1] = b2u(h23);
                    al[mt][jj * 2 + 0] = b2u(__float22bfloat162_rn(d01));
                    al[mt][jj * 2 + 1] = b2u(__float22bfloat162_rn(d23));
                }
            }
            const uint32_t ro = (uint32_t)((t * 16 + lr) * QROW_B);
            #pragma unroll
            for (int db = 0; db < 4; db++) {
                const uint32_t co = (uint32_t)((db * 16 + chk * 8) * 2);
                uint32_t vh[4], vl[4];
                ldm4t(vh, cur + 2 * TILE_B + ro + co);
                ldm4t(vl, cur + 3 * TILE_B + ro + co);
                #pragma unroll
                for (int mt = 0; mt < 2; mt++) {
                    mma_bf16(O[mt][db*2],   ah[mt], vh[0], vh[1]);
                    mma_bf16(O[mt][db*2+1], ah[mt], vh[2], vh[3]);
                    mma_bf16(O[mt][db*2],   al[mt], vh[0], vh[1]);
                    mma_bf16(O[mt][db*2+1], al[mt], vh[2], vh[3]);
                    mma_bf16(O[mt][db*2],   ah[mt], vl[0], vl[1]);
                    mma_bf16(O[mt][db*2+1], ah[mt], vl[2], vl[3]);
                }
            }
        }
        __syncthreads();
    }

    // row-sum reduction across lanes sharing a row
    #pragma unroll
    for (int mt = 0; mt < 2; mt++) {
        lsum[mt][0] += __shfl_xor_sync(0xFFFFFFFFu, lsum[mt][0], 1);
        lsum[mt][0] += __shfl_xor_sync(0xFFFFFFFFu, lsum[mt][0], 2);
        lsum[mt][1] += __shfl_xor_sync(0xFFFFFFFFu, lsum[mt][1], 1);
        lsum[mt][1] += __shfl_xor_sync(0xFFFFFFFFu, lsum[mt][1], 2);
    }

    // write normalized output as hi/lo split into [b*S+s][H]
    const int b_idx = head / NHc, h = head % NHc;
    #pragma unroll
    for (int mt = 0; mt < 2; mt++) {
        const int row0 = q0 + wid * 32 + mt * 16 + g;
        const float inv0 = 1.f / lsum[mt][0], inv1 = 1.f / lsum[mt][1];
        #pragma unroll
        for (int j = 0; j < 8; j++) {
            const int dcol = h * DHc + j * 8 + tg * 2;
            {
                const float v0 = O[mt][j][0] * inv0, v1 = O[mt][j][1] * inv0;
                bf16 h0, l0, h1, l1;
                split1(v0, h0, l0); split1(v1, h1, l1);
                const size_t o = (size_t)(b_idx * Sc + row0) * Hc + dcol;
                *(__nv_bfloat162*)(g_Ahi + o) = __halves2bfloat162(h0, h1);
                *(__nv_bfloat162*)(g_Alo + o) = __halves2bfloat162(l0, l1);
            }
            {
                const float v2 = O[mt][j][2] * inv1, v3 = O[mt][j][3] * inv1;
                bf16 h2, l2, h3, l3;
                split1(v2, h2, l2); split1(v3, h3, l3);
                const size_t o = (size_t)(b_idx * Sc + row0 + 8) * Hc + dcol;
                *(__nv_bfloat162*)(g_Ahi + o) = __halves2bfloat162(h2, h3);
                *(__nv_bfloat162*)(g_Alo + o) = __halves2bfloat162(l2, l3);
            }
        }
    }
}

// ---------------------------------------------------------------------------
extern "C" void kernel_launch(void* const* d_in, const int* in_sizes, int n_in,
                              void* d_out, int out_size)
{
    const float* x  = (const float*)d_in[0];
    const float* Wq = (const float*)d_in[2];
    const float* bq = (const float*)d_in[3];
    const float* Wk = (const float*)d_in[4];
    const float* bk = (const float*)d_in[5];
    const float* Wv = (const float*)d_in[6];
    const float* bv = (const float*)d_in[7];
    const float* Wo = (const float*)d_in[8];
    const float* bo = (const float*)d_in[9];
    float* out = (float*)d_out;

    static bool attr_set = false;
    if (!attr_set) {
        cudaFuncSetAttribute(attn_mma_kernel,
                             cudaFuncAttributeMaxDynamicSharedMemorySize, ATTN_SMEM);
        cudaFuncSetAttribute(mma_gemm_qkv,
                             cudaFuncAttributeMaxDynamicSharedMemorySize, GEMM_SMEM);
        cudaFuncSetAttribute(mma_gemm_out,
                             cudaFuncAttributeMaxDynamicSharedMemorySize, GEMM_SMEM);
        attr_set = true;
    }

    // 0) split x and weights into bf16 hi/lo (weights transposed to [n][k])
    split_x_kernel<<<(Mc * Hc / 4) / 256, 256>>>(x);
    dim3 gw(Hc / 32, Hc / 32, 4);
    split_w_kernel<<<gw, 256>>>(Wq, Wk, Wv, Wo);

    // 1) QKV projections (HMMA, cp.async pipelined)
    dim3 g1(Hc / 128, Mc / 128, 3);
    mma_gemm_qkv<<<g1, 256, GEMM_SMEM>>>(bq, bk, bv);

    // 2) flash attention on HMMA, warp m32, register-lean, cp.async pipelined
    dim3 g2(Sc / 256, Bc * NHc);
    attn_mma_kernel<<<g2, 256, ATTN_SMEM>>>();

    // 3) output projection (HMMA, cp.async pipelined)
    dim3 g3(Hc / 128, Mc / 128);
    mma_gemm_out<<<g3, 256, GEMM_SMEM>>>(bo, out);
}

// round 15
// speedup vs baseline: 1.3140x; 1.3140x over previous
#include <cuda_runtime.h>
#include <cuda_bf16.h>
#include <cstdint>

// Problem constants
#define Bc  4
#define Sc  2048
#define Hc  768
#define NHc 12
#define DHc 64
#define Mc  (Bc * Sc)          // 8192
#define SCALE 0.125f

typedef __nv_bfloat16 bf16;

// =================== helpers ================================================
__device__ __forceinline__ uint32_t smem_u32(const void* p) {
    uint32_t a;
    asm("{ .reg .u64 t; cvta.to.shared.u64 t, %1; cvt.u32.u64 %0, t; }" : "=r"(a) : "l"(p));
    return a;
}
__device__ __forceinline__ uint32_t lds32(uint32_t addr) {
    uint32_t v; asm volatile("ld.shared.b32 %0, [%1];" : "=r"(v) : "r"(addr)); return v;
}
__device__ __forceinline__ void ldm4(uint32_t* r, uint32_t addr) {
    asm volatile("ldmatrix.sync.aligned.m8n8.x4.shared.b16 {%0,%1,%2,%3}, [%4];"
        : "=r"(r[0]), "=r"(r[1]), "=r"(r[2]), "=r"(r[3]) : "r"(addr));
}
__device__ __forceinline__ void mma_bf16(float* d, const uint32_t* a, uint32_t b0, uint32_t b1) {
    asm volatile("mma.sync.aligned.m16n8k16.row.col.f32.bf16.bf16.f32 "
        "{%0,%1,%2,%3}, {%4,%5,%6,%7}, {%8,%9}, {%0,%1,%2,%3};"
        : "+f"(d[0]), "+f"(d[1]), "+f"(d[2]), "+f"(d[3])
        : "r"(a[0]), "r"(a[1]), "r"(a[2]), "r"(a[3]), "r"(b0), "r"(b1));
}
// tf32 MMA m16n8k8 (sm_80 baseline)
__device__ __forceinline__ void mma_tf32(float* d, const uint32_t* a, uint32_t b0, uint32_t b1) {
    asm volatile("mma.sync.aligned.m16n8k8.row.col.f32.tf32.tf32.f32 "
        "{%0,%1,%2,%3}, {%4,%5,%6,%7}, {%8,%9}, {%0,%1,%2,%3};"
        : "+f"(d[0]), "+f"(d[1]), "+f"(d[2]), "+f"(d[3])
        : "r"(a[0]), "r"(a[1]), "r"(a[2]), "r"(a[3]), "r"(b0), "r"(b1));
}
__device__ __forceinline__ uint32_t f2tf32(float v) {
    uint32_t u; asm("cvt.rna.tf32.f32 %0, %1;" : "=r"(u) : "f"(v)); return u;
}
// cp.async (sm_80 baseline -> valid on compute_103)
__device__ __forceinline__ void cp16(uint32_t dst, const void* src) {
    asm volatile("cp.async.cg.shared.global [%0], [%1], 16;" :: "r"(dst), "l"(src));
}
#define CP_COMMIT() asm volatile("cp.async.commit_group;" ::: "memory")
#define CP_WAIT(n)  asm volatile("cp.async.wait_group %0;" :: "n"(n) : "memory")

// =================== scratch (device globals) ================================
__device__ float g_Qf[(size_t)Bc * NHc * Sc * DHc];   // tf32-rounded fp32, Q pre-scaled
__device__ float g_Kf[(size_t)Bc * NHc * Sc * DHc];
__device__ float g_Vf[(size_t)Bc * NHc * Sc * DHc];
__device__ bf16 g_Ahi[(size_t)Mc * Hc], g_Alo[(size_t)Mc * Hc];          // attn out split
__device__ bf16 g_Xhi[(size_t)Mc * Hc], g_Xlo[(size_t)Mc * Hc];          // x split
__device__ bf16 g_WtHi[(size_t)4 * Hc * Hc], g_WtLo[(size_t)4 * Hc * Hc]; // W^T [z][n][k]

// =================== split kernels ==========================================
__device__ __forceinline__ void split1(float v, bf16& h, bf16& l) {
    h = __float2bfloat16(v);
    l = __float2bfloat16(v - __bfloat162float(h));
}

__global__ __launch_bounds__(256)
void split_x_kernel(const float* __restrict__ X) {
    const int idx = blockIdx.x * 256 + threadIdx.x;
    float4 v = ((const float4*)X)[idx];
    bf16 h0,h1,h2,h3,l0,l1,l2,l3;
    split1(v.x,h0,l0); split1(v.y,h1,l1); split1(v.z,h2,l2); split1(v.w,h3,l3);
    ((__nv_bfloat162*)g_Xhi)[2*idx]   = __halves2bfloat162(h0,h1);
    ((__nv_bfloat162*)g_Xhi)[2*idx+1] = __halves2bfloat162(h2,h3);
    ((__nv_bfloat162*)g_Xlo)[2*idx]   = __halves2bfloat162(l0,l1);
    ((__nv_bfloat162*)g_Xlo)[2*idx+1] = __halves2bfloat162(l2,l3);
}

// transpose + split: Wt[n][k] = W[k][n]
__global__ __launch_bounds__(256)
void split_w_kernel(const float* __restrict__ Wq, const float* __restrict__ Wk,
                    const float* __restrict__ Wv, const float* __restrict__ Wo) {
    __shared__ float t[32][33];
    const int z = blockIdx.z;
    const float* W = (z == 0) ? Wq : (z == 1) ? Wk : (z == 2) ? Wv : Wo;
    bf16* hi = g_WtHi + (size_t)z * Hc * Hc;
    bf16* lo = g_WtLo + (size_t)z * Hc * Hc;
    const int bx = blockIdx.x * 32;
    const int by = blockIdx.y * 32;
    const int tx = threadIdx.x & 31, ty = (threadIdx.x >> 5) * 4;
    #pragma unroll
    for (int j = 0; j < 4; j++)
        t[ty + j][tx] = W[(size_t)(by + ty + j) * Hc + bx + tx];
    __syncthreads();
    #pragma unroll
    for (int j = 0; j < 4; j++) {
        float v = t[tx][ty + j];
        bf16 h, l; split1(v, h, l);
        hi[(size_t)(bx + ty + j) * Hc + by + tx] = h;
        lo[(size_t)(bx + ty + j) * Hc + by + tx] = l;
    }
}

// =================== mma.sync bf16 GEMM (split fp32, static smem) ===========
// MODE 0: fp32 (+bias) row-major.  MODE 1: tf32-rounded fp32 (+bias,*scale)
// into head layout [b*NH+h][s][d].
#define PADK 40

template <int MODE>
__device__ __forceinline__ void mma_gemm_body(
    const bf16* __restrict__ Ahi, const bf16* __restrict__ Alo,
    const bf16* __restrict__ Bhi, const bf16* __restrict__ Blo,
    const float* __restrict__ bias, float scale,
    float* __restrict__ outF)
{
    __shared__ bf16 sAh[128][PADK], sAl[128][PADK];
    __shared__ bf16 sBh[128][PADK], sBl[128][PADK];

    const int tid = threadIdx.x, lane = tid & 31, wid = tid >> 5;
    const int warp_m = wid >> 1, warp_n = wid & 1;
    const int m0 = blockIdx.y * 128, n0 = blockIdx.x * 128;

    float d[2][8][4];
    #pragma unroll
    for (int mt = 0; mt < 2; mt++)
        #pragma unroll
        for (int nt = 0; nt < 8; nt++)
            #pragma unroll
            for (int i = 0; i < 4; i++) d[mt][nt][i] = 0.f;

    const int lr = lane & 15, chk = lane >> 4;
    const uint32_t baseAh = smem_u32(&sAh[0][0]);
    const uint32_t baseAl = smem_u32(&sAl[0][0]);
    const uint32_t baseBh = smem_u32(&sBh[0][0]);
    const uint32_t baseBl = smem_u32(&sBl[0][0]);

    #pragma unroll 1
    for (int c = 0; c < Hc / 32; c++) {
        const int k0 = c * 32;
        #pragma unroll
        for (int p = 0; p < 2; p++) {
            const int idx = tid + p * 256;
            const int r = idx >> 2, cc = idx & 3;
            const size_t goA = (size_t)(m0 + r) * Hc + k0 + cc * 8;
            const size_t goB = (size_t)(n0 + r) * Hc + k0 + cc * 8;
            *(uint4*)&sAh[r][cc * 8] = *(const uint4*)(Ahi + goA);
            *(uint4*)&sAl[r][cc * 8] = *(const uint4*)(Alo + goA);
            *(uint4*)&sBh[r][cc * 8] = *(const uint4*)(Bhi + goB);
            *(uint4*)&sBl[r][cc * 8] = *(const uint4*)(Blo + goB);
        }
        __syncthreads();

        #pragma unroll
        for (int s = 0; s < 2; s++) {
            const int kc = s * 16;
            uint32_t ah[2][4], al[2][4];
            #pragma unroll
            for (int mt = 0; mt < 2; mt++) {
                const uint32_t off =
                    (uint32_t)(((warp_m * 32 + mt * 16 + lr) * PADK + kc + chk * 8) * 2);
                ldm4(ah[mt], baseAh + off);
                ldm4(al[mt], baseAl + off);
            }
            #pragma unroll
            for (int nt2 = 0; nt2 < 4; nt2++) {
                const uint32_t off =
                    (uint32_t)(((warp_n * 64 + nt2 * 16 + lr) * PADK + kc + chk * 8) * 2);
                uint32_t tb[4];
                ldm4(tb, baseBh + off);
                #pragma unroll
                for (int mt = 0; mt < 2; mt++) {
                    mma_bf16(d[mt][nt2 * 2],     ah[mt], tb[0], tb[2]);
                    mma_bf16(d[mt][nt2 * 2 + 1], ah[mt], tb[1], tb[3]);
                    mma_bf16(d[mt][nt2 * 2],     al[mt], tb[0], tb[2]);
                    mma_bf16(d[mt][nt2 * 2 + 1], al[mt], tb[1], tb[3]);
                }
                ldm4(tb, baseBl + off);
                #pragma unroll
                for (int mt = 0; mt < 2; mt++) {
                    mma_bf16(d[mt][nt2 * 2],     ah[mt], tb[0], tb[2]);
                    mma_bf16(d[mt][nt2 * 2 + 1], ah[mt], tb[1], tb[3]);
                }
            }
        }
        __syncthreads();
    }

    const int g = lane >> 2, tg = lane & 3;
    #pragma unroll
    for (int mt = 0; mt < 2; mt++) {
        #pragma unroll
        for (int nt = 0; nt < 8; nt++) {
            const int n  = n0 + warp_n * 64 + nt * 8 + tg * 2;
            const float b0 = bias[n], b1 = bias[n + 1];
            #pragma unroll
            for (int half = 0; half < 2; half++) {
                const int m = m0 + warp_m * 32 + mt * 16 + g + half * 8;
                float v0 = d[mt][nt][half * 2 + 0] + b0;
                float v1 = d[mt][nt][half * 2 + 1] + b1;
                if (MODE == 0) {
                    float2 v; v.x = v0; v.y = v1;
                    *(float2*)(outF + (size_t)m * Hc + n) = v;
                } else {
                    v0 *= scale; v1 *= scale;
                    float2 v;
                    v.x = __uint_as_float(f2tf32(v0));
                    v.y = __uint_as_float(f2tf32(v1));
                    const int bb = m >> 11, sI = m & (Sc - 1);
                    const int h = n >> 6, dd = n & 63;
                    const size_t o = (((size_t)(bb * NHc + h)) * Sc + sI) * DHc + dd;
                    *(float2*)(outF + o) = v;
                }
            }
        }
    }
}

__global__ __launch_bounds__(256, 2)
void mma_gemm_qkv(const float* __restrict__ bq, const float* __restrict__ bk,
                  const float* __restrict__ bv)
{
    const int z = blockIdx.z;
    const float* bias = (z == 0) ? bq : (z == 1) ? bk : bv;
    float* out        = (z == 0) ? g_Qf : (z == 1) ? g_Kf : g_Vf;
    const float scale = (z == 0) ? SCALE : 1.0f;
    mma_gemm_body<1>(g_Xhi, g_Xlo,
                     g_WtHi + (size_t)z * Hc * Hc, g_WtLo + (size_t)z * Hc * Hc,
                     bias, scale, out);
}

__global__ __launch_bounds__(256, 2)
void mma_gemm_out(const float* __restrict__ bo, float* __restrict__ out)
{
    mma_gemm_body<0>(g_Ahi, g_Alo,
                     g_WtHi + (size_t)3 * Hc * Hc, g_WtLo + (size_t)3 * Hc * Hc,
                     bo, 1.0f, out);
}

// =================== flash attention: pure tf32 HMMA ========================
// Q/K/V are tf32-rounded fp32 (ε≈2^-11). Round-7 calibration: final rel err
// ≈ 0.6·ε_operand → ~3e-4 here (vs 1e-3 threshold). 256 mma.m16n8k8 per
// warp-tile vs 384 k16 before (×0.67 tensor work), no hi/lo packing.
// Output still written as bf16 hi/lo split for the accurate O-projection.
#define QSTR 68                        // Q/K row stride in words (272B): banks 4g+tg
#define VSTR 72                        // V row stride in words (288B): banks 8tg+g
#define SM_Q 0
#define QBYTES (256 * QSTR * 4)        // 69632
#define SM_KV QBYTES
#define KTILE_B (64 * QSTR * 4)        // 17408
#define VTILE_B (64 * VSTR * 4)        // 18432
#define KVSTG (KTILE_B + VTILE_B)      // 35840
#define ATTN_SMEM (QBYTES + 2 * KVSTG) // 141312

__global__ __launch_bounds__(256, 1)
void attn_mma_kernel()
{
    extern __shared__ char smem[];
    const uint32_t sb = smem_u32(smem);

    const int tid = threadIdx.x, lane = tid & 31, wid = tid >> 5;
    const int head = blockIdx.y;
    const int q0   = blockIdx.x * 256;
    const int g = lane >> 2, tg = lane & 3;

    const float* Qp = g_Qf + ((size_t)head * Sc + q0) * DHc;
    const float* Kp = g_Kf + (size_t)head * Sc * DHc;
    const float* Vp = g_Vf + (size_t)head * Sc * DHc;

    // ---- prologue: stage Q (256x64 f32) + K/V tile 0 ----
    {
        #pragma unroll
        for (int p = 0; p < 16; p++) {                 // Q: 4096 16B chunks
            const int i = p * 256 + tid;
            const int r = i >> 4, c = i & 15;
            cp16(sb + SM_Q + (uint32_t)(r * QSTR * 4 + c * 16), Qp + r * DHc + c * 4);
        }
        const uint32_t kb = sb + SM_KV, vb = kb + KTILE_B;
        #pragma unroll
        for (int p = 0; p < 4; p++) {                  // K,V: 1024 chunks each
            const int i = p * 256 + tid;
            const int r = i >> 4, c = i & 15;
            cp16(kb + (uint32_t)(r * QSTR * 4 + c * 16), Kp + r * DHc + c * 4);
            cp16(vb + (uint32_t)(r * VSTR * 4 + c * 16), Vp + r * DHc + c * 4);
        }
        CP_COMMIT();
    }

    float O[2][8][4];
    #pragma unroll
    for (int mt = 0; mt < 2; mt++)
        #pragma unroll
        for (int j = 0; j < 8; j++)
            #pragma unroll
            for (int i = 0; i < 4; i++) O[mt][j][i] = 0.f;
    float lsum[2][2] = {{0.f, 0.f}, {0.f, 0.f}};

    const uint32_t srcA = (uint32_t)((lane & ~3) | (tg >> 1));
    const uint32_t srcB = srcA + 2;
    const int selhi = tg & 1;

    #pragma unroll 1
    for (int kt = 0; kt < Sc / 64; kt++) {
        const uint32_t kb = sb + SM_KV + (uint32_t)(kt & 1) * KVSTG;
        const uint32_t vb = kb + KTILE_B;

        if (kt + 1 < Sc / 64) {
            const uint32_t kbn = sb + SM_KV + (uint32_t)((kt + 1) & 1) * KVSTG;
            const uint32_t vbn = kbn + KTILE_B;
            #pragma unroll
            for (int p = 0; p < 4; p++) {
                const int i = p * 256 + tid;
                const int r = i >> 4, c = i & 15;
                const float* ks = Kp + (size_t)((kt + 1) * 64 + r) * DHc + c * 4;
                const float* vs = Vp + (size_t)((kt + 1) * 64 + r) * DHc + c * 4;
                cp16(kbn + (uint32_t)(r * QSTR * 4 + c * 16), ks);
                cp16(vbn + (uint32_t)(r * VSTR * 4 + c * 16), vs);
            }
            CP_COMMIT();
            CP_WAIT(1);
        } else {
            CP_WAIT(0);
        }
        __syncthreads();

        // ---- scores: S = Q . K^T (tf32, k8 steps over d) ----
        float S[2][8][4];
        #pragma unroll
        for (int mt = 0; mt < 2; mt++)
            #pragma unroll
            for (int j = 0; j < 8; j++)
                #pragma unroll
                for (int i = 0; i < 4; i++) S[mt][j][i] = 0.f;

        #pragma unroll
        for (int ks = 0; ks < 8; ks++) {
            const uint32_t col = (uint32_t)(ks * 8 + tg) * 4;
            uint32_t qa[2][4];
            #pragma unroll
            for (int mt = 0; mt < 2; mt++) {
                const uint32_t qaddr =
                    sb + SM_Q + (uint32_t)((wid * 32 + mt * 16 + g) * QSTR) * 4 + col;
                qa[mt][0] = lds32(qaddr);
                qa[mt][1] = lds32(qaddr + 8 * QSTR * 4);
                qa[mt][2] = lds32(qaddr + 16);
                qa[mt][3] = lds32(qaddr + 8 * QSTR * 4 + 16);
            }
            #pragma unroll
            for (int nb = 0; nb < 8; nb++) {
                const uint32_t kaddr = kb + (uint32_t)((nb * 8 + g) * QSTR) * 4 + col;
                const uint32_t b0 = lds32(kaddr);
                const uint32_t b1 = lds32(kaddr + 16);
                mma_tf32(S[0][nb], qa[0], b0, b1);
                mma_tf32(S[1][nb], qa[1], b0, b1);
            }
        }

        // ---- fused softmax + PV per 8-key group t ----
        #pragma unroll
        for (int t = 0; t < 8; t++) {
            uint32_t aa[2][4];
            #pragma unroll
            for (int mt = 0; mt < 2; mt++) {
                const float p0 = __expf(S[mt][t][0]);
                const float p1 = __expf(S[mt][t][1]);
                const float p2 = __expf(S[mt][t][2]);
                const float p3 = __expf(S[mt][t][3]);
                lsum[mt][0] += p0 + p1;
                lsum[mt][1] += p2 + p3;
                const uint32_t u0 = f2tf32(p0), u1 = f2tf32(p1);
                const uint32_t u2 = f2tf32(p2), u3 = f2tf32(p3);
                // c-frag (cols 2tg,2tg+1) -> a-frag (cols tg, tg+4) via shfl
                uint32_t x, y;
                x = __shfl_sync(0xFFFFFFFFu, u0, srcA);
                y = __shfl_sync(0xFFFFFFFFu, u1, srcA);
                aa[mt][0] = selhi ? y : x;
                x = __shfl_sync(0xFFFFFFFFu, u2, srcA);
                y = __shfl_sync(0xFFFFFFFFu, u3, srcA);
                aa[mt][1] = selhi ? y : x;
                x = __shfl_sync(0xFFFFFFFFu, u0, srcB);
                y = __shfl_sync(0xFFFFFFFFu, u1, srcB);
                aa[mt][2] = selhi ? y : x;
                x = __shfl_sync(0xFFFFFFFFu, u2, srcB);
                y = __shfl_sync(0xFFFFFFFFu, u3, srcB);
                aa[mt][3] = selhi ? y : x;
            }
            #pragma unroll
            for (int db = 0; db < 8; db++) {
                const uint32_t vaddr =
                    vb + (uint32_t)((t * 8 + tg) * VSTR + db * 8 + g) * 4;
                const uint32_t b0 = lds32(vaddr);
                const uint32_t b1 = lds32(vaddr + 4 * VSTR * 4);
                mma_tf32(O[0][db], aa[0], b0, b1);
                mma_tf32(O[1][db], aa[1], b0, b1);
            }
        }
        __syncthreads();
    }

    // row-sum reduction across lanes sharing a row
    #pragma unroll
    for (int mt = 0; mt < 2; mt++) {
        lsum[mt][0] += __shfl_xor_sync(0xFFFFFFFFu, lsum[mt][0], 1);
        lsum[mt][0] += __shfl_xor_sync(0xFFFFFFFFu, lsum[mt][0], 2);
        lsum[mt][1] += __shfl_xor_sync(0xFFFFFFFFu, lsum[mt][1], 1);
        lsum[mt][1] += __shfl_xor_sync(0xFFFFFFFFu, lsum[mt][1], 2);
    }

    // write normalized output as hi/lo split into [b*S+s][H]
    const int b_idx = head / NHc, h = head % NHc;
    #pragma unroll
    for (int mt = 0; mt < 2; mt++) {
        const int row0 = q0 + wid * 32 + mt * 16 + g;
        const float inv0 = 1.f / lsum[mt][0], inv1 = 1.f / lsum[mt][1];
        #pragma unroll
        for (int j = 0; j < 8; j++) {
            const int dcol = h * DHc + j * 8 + tg * 2;
            {
                const float v0 = O[mt][j][0] * inv0, v1 = O[mt][j][1] * inv0;
                bf16 h0, l0, h1, l1;
                split1(v0, h0, l0); split1(v1, h1, l1);
                const size_t o = (size_t)(b_idx * Sc + row0) * Hc + dcol;
                *(__nv_bfloat162*)(g_Ahi + o) = __halves2bfloat162(h0, h1);
                *(__nv_bfloat162*)(g_Alo + o) = __halves2bfloat162(l0, l1);
            }
            {
                const float v2 = O[mt][j][2] * inv1, v3 = O[mt][j][3] * inv1;
                bf16 h2, l2, h3, l3;
                split1(v2, h2, l2); split1(v3, h3, l3);
                const size_t o = (size_t)(b_idx * Sc + row0 + 8) * Hc + dcol;
                *(__nv_bfloat162*)(g_Ahi + o) = __halves2bfloat162(h2, h3);
                *(__nv_bfloat162*)(g_Alo + o) = __halves2bfloat162(l2, l3);
            }
        }
    }
}

// ---------------------------------------------------------------------------
extern "C" void kernel_launch(void* const* d_in, const int* in_sizes, int n_in,
                              void* d_out, int out_size)
{
    const float* x  = (const float*)d_in[0];
    const float* Wq = (const float*)d_in[2];
    const float* bq = (const float*)d_in[3];
    const float* Wk = (const float*)d_in[4];
    const float* bk = (const float*)d_in[5];
    const float* Wv = (const float*)d_in[6];
    const float* bv = (const float*)d_in[7];
    const float* Wo = (const float*)d_in[8];
    const float* bo = (const float*)d_in[9];
    float* out = (float*)d_out;

    static bool attr_set = false;
    if (!attr_set) {
        cudaFuncSetAttribute(attn_mma_kernel,
                             cudaFuncAttributeMaxDynamicSharedMemorySize, ATTN_SMEM);
        attr_set = true;
    }

    // 0) split x and weights into bf16 hi/lo (weights transposed to [n][k])
    split_x_kernel<<<(Mc * Hc / 4) / 256, 256>>>(x);
    dim3 gw(Hc / 32, Hc / 32, 4);
    split_w_kernel<<<gw, 256>>>(Wq, Wk, Wv, Wo);

    // 1) QKV projections (split-bf16 HMMA) -> tf32-rounded fp32 head layout
    dim3 g1(Hc / 128, Mc / 128, 3);
    mma_gemm_qkv<<<g1, 256>>>(bq, bk, bv);

    // 2) pure-tf32 flash attention, cp.async double buffered
    dim3 g2(Sc / 256, Bc * NHc);
    attn_mma_kernel<<<g2, 256, ATTN_SMEM>>>();

    // 3) output projection (split-bf16 HMMA)
    dim3 g3(Hc / 128, Mc / 128);
    mma_gemm_out<<<g3, 256>>>(bo, out);
}